// round 4
// baseline (speedup 1.0000x reference)
#include <cuda_runtime.h>
#include <cuda_bf16.h>

// CubEcc2d: Euler characteristic curve of sublevel cubical complex.
// x: [B=32, C=16, H=128, W=128] f32  ->  out: [B,C,RES=64] f32
//
// R4: i8 per-thread histograms (8KB smem -> ~2x occupancy), dp4a byte reduce,
// int4 zeroing, warp-per-image shuffle-scan final kernel.

#define NT 128
#define RES 64
#define STRIPS 4
#define SROWS 32

__device__ int g_part[512 * STRIPS * RES];

__global__ __launch_bounds__(NT, 16)
void strip_kernel(const float* __restrict__ x)
{
    __shared__ signed char hist8[RES * NT];     // 8 KB, hist8[t*128 + tid]
    const int tid = threadIdx.x;

    // zero via int4: 8192B = 512 int4, 4 per thread
    {
        int4* z = (int4*)hist8;
        #pragma unroll
        for (int i = 0; i < 4; i++) z[tid + i * NT] = make_int4(0, 0, 0, 0);
    }
    __syncthreads();

    const int img   = blockIdx.x >> 2;
    const int strip = blockIdx.x & 3;
    const int a0    = strip * SROWS;
    const float* __restrict__ im = x + (size_t)img * (128 * 128);

    const int b    = tid;
    const int bp1  = min(b + 1, 127);           // lane 127: r = v (gated off)
    const int valH = (b < 127) ? -1 : 0;        // h-edge sign, loop-invariant
    const int valF = (b < 127) ?  1 : 0;        // face sign, loop-invariant

    signed char* __restrict__ hcol = hist8 + tid;

    // seed: bins of row a0
    float v = im[a0 * 128 + b];
    float r = im[a0 * 128 + bp1];
    int tv = min(63, __float2int_ru(v * 63.0f));
    int tr = min(63, __float2int_ru(r * 63.0f));

    const int full = min(a0 + SROWS, 127) - a0; // 32, except last strip: 31
    const float* nrow = im + (a0 + 1) * 128;

    #pragma unroll 4
    for (int it = 0; it < full; it++) {
        float nv = nrow[b];
        float nr = nrow[bp1];
        nrow += 128;

        int tnv = min(63, __float2int_ru(nv * 63.0f));
        int tnr = min(63, __float2int_ru(nr * 63.0f));

        int th = max(tv, tr);                   // h-edge bin
        int te = max(tv, tnv);                  // v-edge bin
        int tf = max(th, max(tnv, tnr));        // face bin

        hcol[tv << 7] += 1;                     // vertex (+)
        hcol[th << 7] += (signed char)valH;     // h-edge (-)
        hcol[te << 7] -= 1;                     // v-edge (-)
        hcol[tf << 7] += (signed char)valF;     // face   (+)

        tv = tnv; tr = tnr;
    }

    // tail row a=127 (last strip only)
    if (a0 + SROWS == 128) {
        hcol[tv << 7] += 1;
        hcol[max(tv, tr) << 7] += (signed char)valH;
    }
    __syncthreads();

    // reduce: 128 i8 columns -> 64 bins via dp4a over u32 words.
    // 32 words per bin row; skew (i+bin)&31 -> conflict-free within warp.
    if (tid < RES) {
        const int bin = tid;
        const unsigned int* __restrict__ row = (const unsigned int*)hist8 + (bin << 5);
        int sum = 0;
        #pragma unroll 8
        for (int i = 0; i < 32; i++) {
            int w = (i + bin) & 31;
            sum = __dp4a((int)row[w], 0x01010101, sum);
        }
        g_part[blockIdx.x * RES + bin] = sum;
    }
}

__global__ __launch_bounds__(NT)
void final_kernel(float* __restrict__ out)
{
    // one warp per image; lane holds bins (lane) and (lane+32)
    const int img  = blockIdx.x * 4 + (threadIdx.x >> 5);
    const int lane = threadIdx.x & 31;
    const int base = img * STRIPS * RES;

    int a = 0, bsum = 0;
    #pragma unroll
    for (int s = 0; s < STRIPS; s++) {
        a    += g_part[base + s * RES + lane];
        bsum += g_part[base + s * RES + 32 + lane];
    }

    // inclusive scan over 64 values: scan a, scan b, then b += total(a)
    #pragma unroll
    for (int s = 1; s < 32; s <<= 1) {
        int n = __shfl_up_sync(0xffffffff, a, s);
        if (lane >= s) a += n;
    }
    #pragma unroll
    for (int s = 1; s < 32; s <<= 1) {
        int n = __shfl_up_sync(0xffffffff, bsum, s);
        if (lane >= s) bsum += n;
    }
    bsum += __shfl_sync(0xffffffff, a, 31);

    out[img * RES + lane]      = (float)a;
    out[img * RES + 32 + lane] = (float)bsum;
}

extern "C" void kernel_launch(void* const* d_in, const int* in_sizes, int n_in,
                              void* d_out, int out_size)
{
    const float* x = (const float*)d_in[0];
    float* out = (float*)d_out;
    strip_kernel<<<512 * STRIPS, NT>>>(x);
    final_kernel<<<128, NT>>>(out);
}

// round 5
// speedup vs baseline: 1.6567x; 1.6567x over previous
#include <cuda_runtime.h>
#include <cuda_bf16.h>

// CubEcc2d: Euler characteristic curve of sublevel cubical complex.
// x: [B=32, C=16, H=128, W=128] f32  ->  out: [B,C,RES=64] f32
//
// R5: lower-star decomposition. Each cell is claimed by its maximal vertex
// under the total order (value, linear index); each vertex does ONE smem RMW
// adding s = 1 - E + F at bin(v). i16 counters, permuted conflict-free layout,
// 16KB smem. Ties handled exactly: earlier-index neighbor uses <=, later uses <.

#define NT 128
#define RES 64
#define STRIPS 4
#define SROWS 32

__device__ int g_part[512 * STRIPS * RES];   // [img][bin][strip]

__device__ __forceinline__ void body(short* __restrict__ hcol,
                                     float ul, float u, float ur,
                                     float l,  float v, float r,
                                     float nl, float nv, float nr)
{
    const int iv  = __float_as_int(v);
    const int bl  = (__float_as_int(l)  <= iv);   // earlier index
    const int bu  = (__float_as_int(u)  <= iv);
    const int bul = (__float_as_int(ul) <= iv);
    const int bur = (__float_as_int(ur) <= iv);
    const int br  = (__float_as_int(r)  <  iv);   // later index
    const int bnl = (__float_as_int(nl) <  iv);
    const int bnv = (__float_as_int(nv) <  iv);
    const int bnr = (__float_as_int(nr) <  iv);

    int s = 1 - bl - br - bu - bnv
          + (bul & bu & bl)          // NW face
          + (bu & bur & br)          // NE face
          + (bl & bnl & bnv)         // SW face
          + (br & bnv & bnr);        // SE face

    int t = min(63, __float2int_ru(v * 63.0f));
    hcol[t << 7] = (short)(hcol[t << 7] + s);
}

__global__ __launch_bounds__(NT, 12)
void strip_kernel(const float* __restrict__ x)
{
    __shared__ short hist[RES * NT];            // 16 KB
    const int tid = threadIdx.x;

    {   // zero: 16384B = 1024 int4
        int4* z = (int4*)hist;
        #pragma unroll
        for (int i = 0; i < 8; i++) z[tid + i * NT] = make_int4(0, 0, 0, 0);
    }
    __syncthreads();

    const int img   = blockIdx.x >> 2;
    const int strip = blockIdx.x & 3;
    const int a0    = strip * SROWS;
    const float* __restrict__ im = x + (size_t)img * (128 * 128);

    const float INF = __int_as_float(0x7f800000);
    const int b = tid;
    const bool hl = (b > 0), hr = (b < 127);

    // permuted conflict-free i16 column: warp-lane -> distinct bank
    short* __restrict__ hcol = hist + (((tid & 63) << 1) | (tid >> 6));

    // seed rows a0-1 (u) and a0 (c)
    float ul, u, ur, l, v, r;
    if (strip > 0) {
        const float* prow = im + (a0 - 1) * 128;
        ul = hl ? prow[b - 1] : INF;
        u  = prow[b];
        ur = hr ? prow[b + 1] : INF;
    } else { ul = u = ur = INF; }
    {
        const float* crow = im + a0 * 128;
        l = hl ? crow[b - 1] : INF;
        v = crow[b];
        r = hr ? crow[b + 1] : INF;
    }

    const int nfull = (strip == 3) ? (SROWS - 1) : SROWS;
    const float* nrow = im + (a0 + 1) * 128;

    #pragma unroll 4
    for (int it = 0; it < nfull; it++) {
        float nl = hl ? nrow[b - 1] : INF;
        float nv = nrow[b];
        float nr = hr ? nrow[b + 1] : INF;
        nrow += 128;

        body(hcol, ul, u, ur, l, v, r, nl, nv, nr);

        ul = l; u = v; ur = r;
        l = nl; v = nv; r = nr;
    }
    if (strip == 3)   // bottom row a=127: no next row
        body(hcol, ul, u, ur, l, v, r, INF, INF, INF);

    __syncthreads();

    // reduce 128 i16 columns -> 64 bins; words skewed -> conflict-free
    if (tid < RES) {
        const unsigned* __restrict__ row = (const unsigned*)hist + (tid << 6);
        int sum = 0;
        #pragma unroll 8
        for (int i = 0; i < 64; i++) {
            int w = (int)row[(i + tid) & 63];
            sum += ((w << 16) >> 16) + (w >> 16);
        }
        g_part[img * (RES * STRIPS) + (tid << 2) + strip] = sum;
    }
}

__global__ __launch_bounds__(NT)
void final_kernel(float* __restrict__ out)
{
    // one warp per image, lane holds bins lane and lane+32
    const int img  = blockIdx.x * 4 + (threadIdx.x >> 5);
    const int lane = threadIdx.x & 31;

    const int4* gp = (const int4*)g_part + img * RES + lane;
    int4 p0 = gp[0];        // bin = lane, strips 0..3
    int4 p1 = gp[32];       // bin = lane+32
    int a  = p0.x + p0.y + p0.z + p0.w;
    int b2 = p1.x + p1.y + p1.z + p1.w;

    #pragma unroll
    for (int s = 1; s < 32; s <<= 1) {
        int n = __shfl_up_sync(0xffffffff, a, s);
        if (lane >= s) a += n;
    }
    #pragma unroll
    for (int s = 1; s < 32; s <<= 1) {
        int n = __shfl_up_sync(0xffffffff, b2, s);
        if (lane >= s) b2 += n;
    }
    b2 += __shfl_sync(0xffffffff, a, 31);

    out[img * RES + lane]      = (float)a;
    out[img * RES + 32 + lane] = (float)b2;
}

extern "C" void kernel_launch(void* const* d_in, const int* in_sizes, int n_in,
                              void* d_out, int out_size)
{
    const float* x = (const float*)d_in[0];
    float* out = (float*)d_out;
    strip_kernel<<<512 * STRIPS, NT>>>(x);
    final_kernel<<<128, NT>>>(out);
}